// round 7
// baseline (speedup 1.0000x reference)
#include <cuda_runtime.h>
#include <cstdint>

// Problem constants (from reference setup_inputs)
#define PB 16
#define PL 4096
#define PD 768
#define PS 128
#define D4 (PD / 4)          // 192 float4 per row
#define THREADS D4           // one float4 column per thread
#define NWARPS (THREADS / 32)

// One CTA per (b, segment-pair). Grid = B * S/2 = 1024 -> single wave at
// occ=8 on 148 SMs (vs 2048 CTAs = 1.73 waves). The two segments are adjacent
// token ranges, so the CTA streams one contiguous slice. The segment start is
// computed in-CTA by a block reduction over the (L2-cached) lengths row,
// eliminating the separate scan kernel.
__global__ __launch_bounds__(THREADS) void pooling_kernel(
    const float* __restrict__ wv,            // [B, L, D]
    const int* __restrict__ rep_ids,         // [B, S]
    const int* __restrict__ rep_mask,        // [B, S] bool as int32
    const int* __restrict__ lengths,         // [B, S]
    const int* __restrict__ len_mask,        // [B, S] bool as int32
    float* __restrict__ out,                 // [B, 2S, D] (+ mask tail)
    int write_mask)
{
    const int blk = blockIdx.x;
    const int b = blk >> 6;              // / (PS/2)
    const int s0 = (blk & 63) << 1;      // first of the two segments
    const int tid = threadIdx.x;
    const int lane = tid & 31;
    const int wid = tid >> 5;

    __shared__ int sred[NWARPS];

    // ---- start0 = sum_{j < s0} lengths[b, j] (block reduction) ----
    const int* lrow = lengths + b * PS;
    int part = (tid < s0) ? __ldg(&lrow[tid]) : 0;   // tid<192, s0<=126
#pragma unroll
    for (int o = 16; o > 0; o >>= 1)
        part += __shfl_down_sync(0xffffffffu, part, o);
    if (lane == 0) sred[wid] = part;
    __syncthreads();
    int start = 0;
#pragma unroll
    for (int w = 0; w < NWARPS; w++) start += sred[w];

    const float4* __restrict__ wvb =
        reinterpret_cast<const float4*>(wv) + (unsigned)b * (PL * D4);
    float4* __restrict__ outb =
        reinterpret_cast<float4*>(out) + (unsigned)b * (2 * PS * D4);

    for (int seg = 0; seg < 2; seg++) {
        const int s = s0 + seg;
        const int bs = b * PS + s;

        int len = __ldg(&lengths[bs]);
        int st = start;
        int end = st + len;
        if (st > PL) st = PL;
        if (end > PL) end = PL;
        start += len;   // next segment begins where this one ends

        const float4* __restrict__ p = wvb + (unsigned)st * D4 + tid;

        float4 a0 = make_float4(0.f, 0.f, 0.f, 0.f);
        float4 a1 = make_float4(0.f, 0.f, 0.f, 0.f);
        int cx = 0, cy = 0, cz = 0, cw = 0;

        int n = end - st;
        int n8 = n >> 3;
        for (int i = 0; i < n8; i++) {
            float4 v0 = __ldg(p + 0 * D4);
            float4 v1 = __ldg(p + 1 * D4);
            float4 v2 = __ldg(p + 2 * D4);
            float4 v3 = __ldg(p + 3 * D4);
            float4 v4 = __ldg(p + 4 * D4);
            float4 v5 = __ldg(p + 5 * D4);
            float4 v6 = __ldg(p + 6 * D4);
            float4 v7 = __ldg(p + 7 * D4);
            p += 8 * D4;

            a0.x += v0.x; a0.y += v0.y; a0.z += v0.z; a0.w += v0.w;
            a1.x += v1.x; a1.y += v1.y; a1.z += v1.z; a1.w += v1.w;
            a0.x += v2.x; a0.y += v2.y; a0.z += v2.z; a0.w += v2.w;
            a1.x += v3.x; a1.y += v3.y; a1.z += v3.z; a1.w += v3.w;
            a0.x += v4.x; a0.y += v4.y; a0.z += v4.z; a0.w += v4.w;
            a1.x += v5.x; a1.y += v5.y; a1.z += v5.z; a1.w += v5.w;
            a0.x += v6.x; a0.y += v6.y; a0.z += v6.z; a0.w += v6.w;
            a1.x += v7.x; a1.y += v7.y; a1.z += v7.z; a1.w += v7.w;

            cx += (v0.x != 0.f) + (v1.x != 0.f) + (v2.x != 0.f) + (v3.x != 0.f)
                + (v4.x != 0.f) + (v5.x != 0.f) + (v6.x != 0.f) + (v7.x != 0.f);
            cy += (v0.y != 0.f) + (v1.y != 0.f) + (v2.y != 0.f) + (v3.y != 0.f)
                + (v4.y != 0.f) + (v5.y != 0.f) + (v6.y != 0.f) + (v7.y != 0.f);
            cz += (v0.z != 0.f) + (v1.z != 0.f) + (v2.z != 0.f) + (v3.z != 0.f)
                + (v4.z != 0.f) + (v5.z != 0.f) + (v6.z != 0.f) + (v7.z != 0.f);
            cw += (v0.w != 0.f) + (v1.w != 0.f) + (v2.w != 0.f) + (v3.w != 0.f)
                + (v4.w != 0.f) + (v5.w != 0.f) + (v6.w != 0.f) + (v7.w != 0.f);
        }
        for (int r = n & 7; r > 0; r--) {
            float4 v = __ldg(p);
            p += D4;
            a0.x += v.x; a0.y += v.y; a0.z += v.z; a0.w += v.w;
            cx += (v.x != 0.f); cy += (v.y != 0.f);
            cz += (v.z != 0.f); cw += (v.w != 0.f);
        }
        float4 acc = make_float4(a0.x + a1.x, a0.y + a1.y,
                                 a0.z + a1.z, a0.w + a1.w);

        // ---- block-reduce total nonzero count ----
        int nz = cx + cy + cz + cw;
#pragma unroll
        for (int o = 16; o > 0; o >>= 1)
            nz += __shfl_down_sync(0xffffffffu, nz, o);
        __syncthreads();               // protect sred reuse across iterations
        if (lane == 0) sred[wid] = nz;
        __syncthreads();
        int total_nz = 0;
#pragma unroll
        for (int w = 0; w < NWARPS; w++) total_nz += sred[w];

        const float mlen = len_mask[bs] ? 1.f : 0.f;
        const float mrep = rep_mask[bs] ? 1.f : 0.f;

        float4 mv;
        if (total_nz == 0) {
            mv = __ldg(&reinterpret_cast<const float4*>(wv)[tid]);  // wv[0,0,:]
        } else {
            mv.x = acc.x / (float)(cx ? cx : 1);
            mv.y = acc.y / (float)(cy ? cy : 1);
            mv.z = acc.z / (float)(cz ? cz : 1);
            mv.w = acc.w / (float)(cw ? cw : 1);
        }
        mv.x *= mlen; mv.y *= mlen; mv.z *= mlen; mv.w *= mlen;
        outb[(unsigned)(PS + s) * D4 + tid] = mv;

        // ---- gather path ----
        int id = __ldg(&rep_ids[bs]);
        if (id < 0) id = 0;
        if (id >= PL) id = PL - 1;
        float4 g = __ldg(&wvb[(unsigned)id * D4 + tid]);
        g.x *= mrep; g.y *= mrep; g.z *= mrep; g.w *= mrep;
        outb[(unsigned)s * D4 + tid] = g;

        if (write_mask && tid == 0) {
            float* mo = out + (size_t)PB * 2 * PS * PD;
            mo[b * 2 * PS + s] = mrep;
            mo[b * 2 * PS + PS + s] = mlen;
        }
    }
}

extern "C" void kernel_launch(void* const* d_in, const int* in_sizes, int n_in,
                              void* d_out, int out_size) {
    const float* wv = (const float*)d_in[0];
    const int* rep_ids = (const int*)d_in[1];
    const int* rep_mask = (const int*)d_in[2];
    const int* lengths = (const int*)d_in[3];
    const int* len_mask = (const int*)d_in[4];
    float* out = (float*)d_out;

    const int vec_elems = PB * 2 * PS * PD;
    const int write_mask = (out_size > vec_elems) ? 1 : 0;

    pooling_kernel<<<PB * PS / 2, THREADS>>>(wv, rep_ids, rep_mask, lengths,
                                             len_mask, out, write_mask);
}

// round 8
// speedup vs baseline: 1.1620x; 1.1620x over previous
#include <cuda_runtime.h>
#include <cstdint>

// Problem constants (from reference setup_inputs)
#define PB 16
#define PL 4096
#define PD 768
#define PS 128
#define D4 (PD / 4)          // 192 float4 per row
#define THREADS D4           // one float4 column per thread
#define NWARPS (THREADS / 32)

__device__ __forceinline__ void acc4(const float4 (&v)[4], float4& a,
                                     int& cx, int& cy, int& cz, int& cw) {
#pragma unroll
    for (int k = 0; k < 4; k++) {
        a.x += v[k].x; a.y += v[k].y; a.z += v[k].z; a.w += v[k].w;
        cx += (v[k].x != 0.f);
        cy += (v[k].y != 0.f);
        cz += (v[k].z != 0.f);
        cw += (v[k].w != 0.f);
    }
}

__device__ __forceinline__ void ld4(float4 (&v)[4], const float4* __restrict__ p) {
    v[0] = __ldg(p + 0 * D4);
    v[1] = __ldg(p + 1 * D4);
    v[2] = __ldg(p + 2 * D4);
    v[3] = __ldg(p + 3 * D4);
}

// One CTA per (b, s). Explicit 2-stage rotating register pipeline: the next
// 4-token batch's loads are issued BEFORE the previous batch is accumulated,
// so every warp always has a load batch in flight (no burst/drain convoy).
// Gather row is loaded in the prologue to overlap its latency with the stream.
__global__ __launch_bounds__(THREADS) void pooling_kernel(
    const float* __restrict__ wv,            // [B, L, D]
    const int* __restrict__ rep_ids,         // [B, S]
    const int* __restrict__ rep_mask,        // [B, S] bool as int32
    const int* __restrict__ lengths,         // [B, S]
    const int* __restrict__ len_mask,        // [B, S] bool as int32
    float* __restrict__ out,                 // [B, 2S, D] (+ mask tail)
    int write_mask)
{
    const int bs = blockIdx.x;
    const int b = bs >> 7;
    const int s = bs & (PS - 1);
    const int tid = threadIdx.x;
    const int lane = tid & 31;
    const int wid = tid >> 5;

    __shared__ int sred[NWARPS];

    // ---- start = sum_{j < s} lengths[b, j] (block reduction) ----
    const int* lrow = lengths + b * PS;
    int part = (tid < s) ? __ldg(&lrow[tid]) : 0;    // tid<192 covers s<=127
#pragma unroll
    for (int o = 16; o > 0; o >>= 1)
        part += __shfl_down_sync(0xffffffffu, part, o);
    if (lane == 0) sred[wid] = part;
    __syncthreads();
    int start = 0;
#pragma unroll
    for (int w = 0; w < NWARPS; w++) start += sred[w];

    int len = __ldg(&lengths[bs]);
    int end = start + len;
    if (start > PL) start = PL;
    if (end > PL) end = PL;
    const int n = end - start;

    const float4* __restrict__ wvb =
        reinterpret_cast<const float4*>(wv) + (unsigned)b * (PL * D4);

    // ---- early gather load (independent of stream; overlaps latency) ----
    int id = __ldg(&rep_ids[bs]);
    if (id < 0) id = 0;
    if (id >= PL) id = PL - 1;
    float4 g = __ldg(&wvb[(unsigned)id * D4 + tid]);

    // ---- streamed segment sum + per-feature nonzero counts, pipelined ----
    const float4* __restrict__ p = wvb + (unsigned)start * D4 + tid;

    float4 acc = make_float4(0.f, 0.f, 0.f, 0.f);
    int cx = 0, cy = 0, cz = 0, cw = 0;

    float4 va[4], vb[4];
    const int nb = n >> 2;          // number of 4-token batches
    if (nb > 0) {
        ld4(va, p); p += 4 * D4;    // stage fill
        int i = 1;
        for (; i + 1 < nb; i += 2) {
            ld4(vb, p); p += 4 * D4;            // issue B
            acc4(va, acc, cx, cy, cz, cw);      // consume A
            ld4(va, p); p += 4 * D4;            // issue A'
            acc4(vb, acc, cx, cy, cz, cw);      // consume B
        }
        if (i < nb) {               // one remaining full batch
            ld4(vb, p); p += 4 * D4;
            acc4(va, acc, cx, cy, cz, cw);
            acc4(vb, acc, cx, cy, cz, cw);
        } else {
            acc4(va, acc, cx, cy, cz, cw);
        }
    }
    for (int r = n & 3; r > 0; r--) {           // tail tokens
        float4 v = __ldg(p); p += D4;
        acc.x += v.x; acc.y += v.y; acc.z += v.z; acc.w += v.w;
        cx += (v.x != 0.f); cy += (v.y != 0.f);
        cz += (v.z != 0.f); cw += (v.w != 0.f);
    }

    // ---- block-reduce total nonzero count ----
    int nz = cx + cy + cz + cw;
#pragma unroll
    for (int o = 16; o > 0; o >>= 1)
        nz += __shfl_down_sync(0xffffffffu, nz, o);
    __syncthreads();                // sred reuse
    if (lane == 0) sred[wid] = nz;
    __syncthreads();
    int total_nz = 0;
#pragma unroll
    for (int w = 0; w < NWARPS; w++) total_nz += sred[w];

    const float mlen = len_mask[bs] ? 1.f : 0.f;
    const float mrep = rep_mask[bs] ? 1.f : 0.f;

    float4 mv;
    if (total_nz == 0) {
        mv = __ldg(&reinterpret_cast<const float4*>(wv)[tid]);  // wv[0,0,:]
    } else {
        mv.x = acc.x / (float)(cx ? cx : 1);
        mv.y = acc.y / (float)(cy ? cy : 1);
        mv.z = acc.z / (float)(cz ? cz : 1);
        mv.w = acc.w / (float)(cw ? cw : 1);
    }
    mv.x *= mlen; mv.y *= mlen; mv.z *= mlen; mv.w *= mlen;

    float4* __restrict__ outb =
        reinterpret_cast<float4*>(out) + (unsigned)b * (2 * PS * D4);
    __stcs(&outb[(unsigned)(PS + s) * D4 + tid], mv);           // mean row

    g.x *= mrep; g.y *= mrep; g.z *= mrep; g.w *= mrep;
    __stcs(&outb[(unsigned)s * D4 + tid], g);                   // rep row

    if (write_mask && tid == 0) {
        float* mo = out + (size_t)PB * 2 * PS * PD;
        mo[b * 2 * PS + s] = mrep;
        mo[b * 2 * PS + PS + s] = mlen;
    }
}

extern "C" void kernel_launch(void* const* d_in, const int* in_sizes, int n_in,
                              void* d_out, int out_size) {
    const float* wv = (const float*)d_in[0];
    const int* rep_ids = (const int*)d_in[1];
    const int* rep_mask = (const int*)d_in[2];
    const int* lengths = (const int*)d_in[3];
    const int* len_mask = (const int*)d_in[4];
    float* out = (float*)d_out;

    const int vec_elems = PB * 2 * PS * PD;
    const int write_mask = (out_size > vec_elems) ? 1 : 0;

    pooling_kernel<<<PB * PS, THREADS>>>(wv, rep_ids, rep_mask, lengths,
                                         len_mask, out, write_mask);
}